// round 1
// baseline (speedup 1.0000x reference)
#include <cuda_runtime.h>
#include <cuda_bf16.h>
#include <cstddef>

#define HDIM 1024
#define SLEN 4096
#define BATCH 32
#define NSB 8                              // s-blocks per batch
#define ROWS_PER_BLOCK (SLEN / NSB)        // 512
#define NWARPS 8
#define ROWS_PER_WARP (ROWS_PER_BLOCK / NWARPS)  // 64
#define NPART (NSB * NWARPS)               // 64 partials per batch

// Scratch (device globals; no allocation in kernel_launch)
__device__ float g_vpart[4][HDIM];                 // partial U^T V
__device__ float g_scores[BATCH * SLEN];           // raw scores
__device__ float g_pctx[(size_t)BATCH * NPART * HDIM]; // per-warp weighted-sum partials (8 MB)
__device__ float g_pm[BATCH * NPART];
__device__ float g_pl[BATCH * NPART];

// ---------------------------------------------------------------------------
// K1: v'[h] partials = sum_{o in chunk} U[o,h] * V[o]
// grid (8, 4), block 128
// ---------------------------------------------------------------------------
__global__ void vprime_kernel(const float* __restrict__ U,
                              const float* __restrict__ V) {
    int h  = blockIdx.x * 128 + threadIdx.x;
    int oc = blockIdx.y;
    int o0 = oc * 256;
    float acc = 0.0f;
#pragma unroll 4
    for (int o = 0; o < 256; o++) {
        acc += U[(size_t)(o0 + o) * HDIM + h] * V[o0 + o];
    }
    g_vpart[oc][h] = acc;
}

// ---------------------------------------------------------------------------
// K2: single pass over keys. Each warp: 64 contiguous rows of one batch.
// Computes score = k . v', stores raw score, and online-softmax accumulates
// acc[h] = sum exp(score - m) * k[h]. Keys read exactly once.
// grid (NSB, BATCH), block 256
// ---------------------------------------------------------------------------
__global__ void __launch_bounds__(256, 2)
main_pass_kernel(const float* __restrict__ keys) {
    const int b    = blockIdx.y;
    const int sb   = blockIdx.x;
    const int w    = threadIdx.x >> 5;
    const int lane = threadIdx.x & 31;

    // Load v' into registers: lane covers h = i*128 + lane*4 .. +3
    float4 vp[8];
#pragma unroll
    for (int i = 0; i < 8; i++) {
        int idx = i * 32 + lane;  // float4 index
        float4 a0 = reinterpret_cast<const float4*>(g_vpart[0])[idx];
        float4 a1 = reinterpret_cast<const float4*>(g_vpart[1])[idx];
        float4 a2 = reinterpret_cast<const float4*>(g_vpart[2])[idx];
        float4 a3 = reinterpret_cast<const float4*>(g_vpart[3])[idx];
        vp[i].x = a0.x + a1.x + a2.x + a3.x;
        vp[i].y = a0.y + a1.y + a2.y + a3.y;
        vp[i].z = a0.z + a1.z + a2.z + a3.z;
        vp[i].w = a0.w + a1.w + a2.w + a3.w;
    }

    float m = -3.0e38f;
    float l = 0.0f;
    float4 acc[8];
#pragma unroll
    for (int i = 0; i < 8; i++) acc[i] = make_float4(0.f, 0.f, 0.f, 0.f);

    const int s0 = sb * ROWS_PER_BLOCK + w * ROWS_PER_WARP;
    const float4* __restrict__ base =
        reinterpret_cast<const float4*>(keys + (size_t)b * SLEN * HDIM);

    for (int j = 0; j < ROWS_PER_WARP; j++) {
        const int s = s0 + j;
        const float4* __restrict__ row = base + (size_t)s * (HDIM / 4);

        float4 k[8];
#pragma unroll
        for (int i = 0; i < 8; i++) k[i] = row[i * 32 + lane];

        float d = 0.0f;
#pragma unroll
        for (int i = 0; i < 8; i++) {
            d += k[i].x * vp[i].x + k[i].y * vp[i].y +
                 k[i].z * vp[i].z + k[i].w * vp[i].w;
        }
#pragma unroll
        for (int off = 16; off; off >>= 1)
            d += __shfl_xor_sync(0xffffffffu, d, off);

        if (lane == 0) g_scores[b * SLEN + s] = d;

        if (d > m) {  // rare: new running max -> rescale
            float sc = __expf(m - d);
            l *= sc;
#pragma unroll
            for (int i = 0; i < 8; i++) {
                acc[i].x *= sc; acc[i].y *= sc; acc[i].z *= sc; acc[i].w *= sc;
            }
            m = d;
        }
        float p = __expf(d - m);
        l += p;
#pragma unroll
        for (int i = 0; i < 8; i++) {
            acc[i].x += p * k[i].x; acc[i].y += p * k[i].y;
            acc[i].z += p * k[i].z; acc[i].w += p * k[i].w;
        }
    }

    const int pidx = b * NPART + sb * NWARPS + w;
    if (lane == 0) { g_pm[pidx] = m; g_pl[pidx] = l; }
    float4* __restrict__ pctx =
        reinterpret_cast<float4*>(g_pctx + (size_t)pidx * HDIM);
#pragma unroll
    for (int i = 0; i < 8; i++) pctx[i * 32 + lane] = acc[i];
}

// ---------------------------------------------------------------------------
// K3: per-batch merge of 64 partials + final outputs.
// out layout: [context B*H | weight B*S]
// grid BATCH, block 256
// ---------------------------------------------------------------------------
__global__ void combine_kernel(float* __restrict__ out) {
    const int b = blockIdx.x;
    const int t = threadIdx.x;

    __shared__ float s_m[NPART];
    __shared__ float s_l[NPART];
    __shared__ float s_sc[NPART];
    __shared__ float s_M, s_invL;

    if (t < NPART) {
        s_m[t] = g_pm[b * NPART + t];
        s_l[t] = g_pl[b * NPART + t];
    }
    __syncthreads();
    if (t == 0) {
        float M = -3.0e38f;
        for (int p = 0; p < NPART; p++) M = fmaxf(M, s_m[p]);
        float L = 0.0f;
        for (int p = 0; p < NPART; p++) {
            float sc = __expf(s_m[p] - M);
            s_sc[p] = sc;
            L += sc * s_l[p];
        }
        s_M = M;
        s_invL = 1.0f / L;
    }
    __syncthreads();
    const float M = s_M, invL = s_invL;

    // context[b, h]: merge partials (thread t owns float4 at h = t*4)
    float4 sum = make_float4(0.f, 0.f, 0.f, 0.f);
    for (int p = 0; p < NPART; p++) {
        const float sc = s_sc[p];
        float4 v = reinterpret_cast<const float4*>(
            g_pctx + (size_t)(b * NPART + p) * HDIM)[t];
        sum.x += sc * v.x; sum.y += sc * v.y;
        sum.z += sc * v.z; sum.w += sc * v.w;
    }
    sum.x *= invL; sum.y *= invL; sum.z *= invL; sum.w *= invL;
    reinterpret_cast<float4*>(out + (size_t)b * HDIM)[t] = sum;

    // weight[b, s]
    float* __restrict__ wout = out + (size_t)BATCH * HDIM + (size_t)b * SLEN;
    const float* __restrict__ sc_in = g_scores + (size_t)b * SLEN;
    for (int s = t; s < SLEN; s += 256) {
        wout[s] = __expf(sc_in[s] - M) * invL;
    }
}

// ---------------------------------------------------------------------------
extern "C" void kernel_launch(void* const* d_in, const int* in_sizes, int n_in,
                              void* d_out, int out_size) {
    // inputs (metadata order): query, keys, W, U, V
    const float* keys = (const float*)d_in[1];
    const float* U    = (const float*)d_in[3];
    const float* V    = (const float*)d_in[4];
    float* out = (float*)d_out;

    vprime_kernel<<<dim3(8, 4), 128>>>(U, V);
    main_pass_kernel<<<dim3(NSB, BATCH), 256>>>(keys);
    combine_kernel<<<BATCH, 256>>>(out);
}

// round 2
// speedup vs baseline: 1.5043x; 1.5043x over previous
#include <cuda_runtime.h>
#include <cuda_bf16.h>
#include <cstddef>

#define HDIM 1024
#define SLEN 4096
#define BATCH 32
#define NSB 8                              // s-blocks per batch
#define ROWS_PER_BLOCK (SLEN / NSB)        // 512
#define NWARPS 8
#define ROWS_PER_WARP (ROWS_PER_BLOCK / NWARPS)  // 64
#define NPART (NSB * NWARPS)               // 64 partials per batch
#define VCHUNKS 32                         // o-chunks for vprime

// Scratch (device globals; no allocation in kernel_launch)
__device__ float g_vpart[VCHUNKS][HDIM];           // partial U^T V
__device__ float g_vprime[HDIM];                   // reduced U^T V
__device__ float g_scores[BATCH * SLEN];           // raw scores
__device__ float g_pctx[(size_t)BATCH * NPART * HDIM]; // per-warp partials (8 MB)
__device__ float g_pm[BATCH * NPART];
__device__ float g_pl[BATCH * NPART];

// ---------------------------------------------------------------------------
// K1: v' partials. grid (8, 32), block 128. Each block: 32 rows of U for
// 128 h-columns. 256 CTAs -> full-chip, ~2us for the 4MB read.
// ---------------------------------------------------------------------------
__global__ void vprime_kernel(const float* __restrict__ U,
                              const float* __restrict__ V) {
    const int h  = blockIdx.x * 128 + threadIdx.x;
    const int oc = blockIdx.y;
    const int o0 = oc * (HDIM / VCHUNKS);
    float acc = 0.0f;
#pragma unroll 8
    for (int o = 0; o < HDIM / VCHUNKS; o++) {
        acc += U[(size_t)(o0 + o) * HDIM + h] * V[o0 + o];
    }
    g_vpart[oc][h] = acc;
}

// K1b: reduce the 32 partials. grid 8, block 128 (tiny, L2-resident).
__global__ void vreduce_kernel() {
    const int h = blockIdx.x * 128 + threadIdx.x;
    float a = 0.0f;
#pragma unroll
    for (int oc = 0; oc < VCHUNKS; oc++) a += g_vpart[oc][h];
    g_vprime[h] = a;
}

// ---------------------------------------------------------------------------
// K2: single streaming pass over keys (512 MB, read exactly once, __ldcs).
// Each warp: 64 contiguous rows of one batch. score = k . v'; online-softmax
// accumulate acc[h] += exp(score-m)*k[h]. grid (NSB, BATCH), block 256, occ 2.
// ---------------------------------------------------------------------------
__global__ void __launch_bounds__(256, 2)
main_pass_kernel(const float* __restrict__ keys) {
    const int b    = blockIdx.y;
    const int sb   = blockIdx.x;
    const int w    = threadIdx.x >> 5;
    const int lane = threadIdx.x & 31;

    // v' into registers: lane covers float4 index i*32+lane
    float4 vp[8];
#pragma unroll
    for (int i = 0; i < 8; i++)
        vp[i] = reinterpret_cast<const float4*>(g_vprime)[i * 32 + lane];

    float m = -3.0e38f;
    float l = 0.0f;
    float4 acc[8];
#pragma unroll
    for (int i = 0; i < 8; i++) acc[i] = make_float4(0.f, 0.f, 0.f, 0.f);

    const int s0 = sb * ROWS_PER_BLOCK + w * ROWS_PER_WARP;
    const float4* __restrict__ base =
        reinterpret_cast<const float4*>(keys + (size_t)b * SLEN * HDIM);

    for (int j = 0; j < ROWS_PER_WARP; j++) {
        const int s = s0 + j;
        const float4* __restrict__ row = base + (size_t)s * (HDIM / 4);

        float4 k[8];
#pragma unroll
        for (int i = 0; i < 8; i++) k[i] = __ldcs(row + i * 32 + lane);

        float d = 0.0f;
#pragma unroll
        for (int i = 0; i < 8; i++) {
            d += k[i].x * vp[i].x + k[i].y * vp[i].y +
                 k[i].z * vp[i].z + k[i].w * vp[i].w;
        }
#pragma unroll
        for (int off = 16; off; off >>= 1)
            d += __shfl_xor_sync(0xffffffffu, d, off);

        if (lane == 0) g_scores[b * SLEN + s] = d;

        if (d > m) {  // new running max -> rescale
            float sc = __expf(m - d);
            l *= sc;
#pragma unroll
            for (int i = 0; i < 8; i++) {
                acc[i].x *= sc; acc[i].y *= sc; acc[i].z *= sc; acc[i].w *= sc;
            }
            m = d;
        }
        float p = __expf(d - m);
        l += p;
#pragma unroll
        for (int i = 0; i < 8; i++) {
            acc[i].x += p * k[i].x; acc[i].y += p * k[i].y;
            acc[i].z += p * k[i].z; acc[i].w += p * k[i].w;
        }
    }

    const int pidx = b * NPART + sb * NWARPS + w;
    if (lane == 0) { g_pm[pidx] = m; g_pl[pidx] = l; }
    float4* __restrict__ pctx =
        reinterpret_cast<float4*>(g_pctx + (size_t)pidx * HDIM);
#pragma unroll
    for (int i = 0; i < 8; i++) pctx[i * 32 + lane] = acc[i];
}

// ---------------------------------------------------------------------------
// K3: merge 64 partials per batch + emit outputs.
// grid (BATCH, 4), block 256. Each block: 64 float4 h-columns (p split into
// 4 groups of 16, smem-reduced) + 1024 weight values.
// out layout: [context B*H | weight B*S]
// ---------------------------------------------------------------------------
__global__ void combine_kernel(float* __restrict__ out) {
    const int b     = blockIdx.x;
    const int chunk = blockIdx.y;     // 0..3
    const int t     = threadIdx.x;    // 0..255

    __shared__ float  s_sc[NPART];
    __shared__ float  s_M, s_invL;
    __shared__ float4 s_red[4][64];

    if (t == 0) {
        float M = -3.0e38f;
#pragma unroll
        for (int p = 0; p < NPART; p++) M = fmaxf(M, g_pm[b * NPART + p]);
        float L = 0.0f;
#pragma unroll
        for (int p = 0; p < NPART; p++) {
            float sc = __expf(g_pm[b * NPART + p] - M);
            s_sc[p] = sc;
            L += sc * g_pl[b * NPART + p];
        }
        s_M = M;
        s_invL = 1.0f / L;
    }
    __syncthreads();
    const float M = s_M, invL = s_invL;

    // context: h4 = chunk*64 + (t&63); partial group pg = t>>6 covers 16 p's
    const int h4 = chunk * 64 + (t & 63);
    const int pg = t >> 6;
    float4 sum = make_float4(0.f, 0.f, 0.f, 0.f);
#pragma unroll
    for (int pp = 0; pp < 16; pp++) {
        const int p = pg * 16 + pp;
        const float sc = s_sc[p];
        float4 v = reinterpret_cast<const float4*>(
            g_pctx + (size_t)(b * NPART + p) * HDIM)[h4];
        sum.x += sc * v.x; sum.y += sc * v.y;
        sum.z += sc * v.z; sum.w += sc * v.w;
    }
    s_red[pg][t & 63] = sum;
    __syncthreads();
    if (t < 64) {
        float4 a = s_red[0][t], c = s_red[1][t], d = s_red[2][t], e = s_red[3][t];
        a.x = (a.x + c.x + d.x + e.x) * invL;
        a.y = (a.y + c.y + d.y + e.y) * invL;
        a.z = (a.z + c.z + d.z + e.z) * invL;
        a.w = (a.w + c.w + d.w + e.w) * invL;
        reinterpret_cast<float4*>(out + (size_t)b * HDIM)[h4] = a;
    }

    // weight[b, s] for s in [chunk*1024, chunk*1024+1024)
    float* __restrict__ wout = out + (size_t)BATCH * HDIM + (size_t)b * SLEN;
    const float* __restrict__ sc_in = g_scores + (size_t)b * SLEN;
#pragma unroll
    for (int i = 0; i < 4; i++) {
        const int s = chunk * 1024 + i * 256 + t;
        wout[s] = __expf(sc_in[s] - M) * invL;
    }
}

// ---------------------------------------------------------------------------
extern "C" void kernel_launch(void* const* d_in, const int* in_sizes, int n_in,
                              void* d_out, int out_size) {
    // inputs (metadata order): query, keys, W, U, V
    const float* keys = (const float*)d_in[1];
    const float* U    = (const float*)d_in[3];
    const float* V    = (const float*)d_in[4];
    float* out = (float*)d_out;

    vprime_kernel<<<dim3(8, VCHUNKS), 128>>>(U, V);
    vreduce_kernel<<<8, 128>>>();
    main_pass_kernel<<<dim3(NSB, BATCH), 256>>>(keys);
    combine_kernel<<<dim3(BATCH, 4), 256>>>(out);
}

// round 3
// speedup vs baseline: 1.5598x; 1.0369x over previous
#include <cuda_runtime.h>
#include <cuda_bf16.h>
#include <cstddef>

#define HDIM 1024
#define SLEN 4096
#define BATCH 32
#define NSB 8                              // s-blocks per batch
#define ROWS_PER_BLOCK (SLEN / NSB)        // 512
#define NWARPS 8
#define ROWS_PER_WARP (ROWS_PER_BLOCK / NWARPS)  // 64
#define NPART NSB                          // 8 block-level partials per batch
#define VCHUNKS 32                         // o-chunks for vprime

// Scratch (device globals; no allocation in kernel_launch)
__device__ float g_vpart[VCHUNKS][HDIM];           // partial U^T V
__device__ float g_vprime[HDIM];                   // reduced U^T V
__device__ float g_scores[BATCH * SLEN];           // raw scores
__device__ float g_pctx[(size_t)BATCH * NPART * HDIM]; // block partials (1 MB)
__device__ float g_pm[BATCH * NPART];
__device__ float g_pl[BATCH * NPART];

// ---------------------------------------------------------------------------
// K1: v' partials. grid (8, 32), block 128.
// ---------------------------------------------------------------------------
__global__ void vprime_kernel(const float* __restrict__ U,
                              const float* __restrict__ V) {
    const int h  = blockIdx.x * 128 + threadIdx.x;
    const int oc = blockIdx.y;
    const int o0 = oc * (HDIM / VCHUNKS);
    float acc = 0.0f;
#pragma unroll 8
    for (int o = 0; o < HDIM / VCHUNKS; o++) {
        acc += U[(size_t)(o0 + o) * HDIM + h] * V[o0 + o];
    }
    g_vpart[oc][h] = acc;
}

// K1b: reduce the 32 partials. grid 8, block 128.
__global__ void vreduce_kernel() {
    const int h = blockIdx.x * 128 + threadIdx.x;
    float a = 0.0f;
#pragma unroll
    for (int oc = 0; oc < VCHUNKS; oc++) a += g_vpart[oc][h];
    g_vprime[h] = a;
}

// ---------------------------------------------------------------------------
// K2: single streaming pass over keys (512 MB, read once, __ldcs).
// Each warp: 64 rows. Online softmax in registers; at block end the 8 warp
// partials are merged in smem -> ONE partial per block (8 per batch).
// grid (NSB, BATCH), block 256, occ 2.
// ---------------------------------------------------------------------------
__global__ void __launch_bounds__(256, 2)
main_pass_kernel(const float* __restrict__ keys) {
    const int b    = blockIdx.y;
    const int sb   = blockIdx.x;
    const int w    = threadIdx.x >> 5;
    const int lane = threadIdx.x & 31;
    const int t    = threadIdx.x;

    __shared__ float4 s_acc[NWARPS][256];   // 32 KB
    __shared__ float  s_m[NWARPS];
    __shared__ float  s_l[NWARPS];

    // v' into registers: lane covers float4 index i*32+lane
    float4 vp[8];
#pragma unroll
    for (int i = 0; i < 8; i++)
        vp[i] = reinterpret_cast<const float4*>(g_vprime)[i * 32 + lane];

    float m = -3.0e38f;
    float l = 0.0f;
    float4 acc[8];
#pragma unroll
    for (int i = 0; i < 8; i++) acc[i] = make_float4(0.f, 0.f, 0.f, 0.f);

    const int s0 = sb * ROWS_PER_BLOCK + w * ROWS_PER_WARP;
    const float4* __restrict__ base =
        reinterpret_cast<const float4*>(keys + (size_t)b * SLEN * HDIM);

    for (int j = 0; j < ROWS_PER_WARP; j++) {
        const int s = s0 + j;
        const float4* __restrict__ row = base + (size_t)s * (HDIM / 4);

        float4 k[8];
#pragma unroll
        for (int i = 0; i < 8; i++) k[i] = __ldcs(row + i * 32 + lane);

        float d = 0.0f;
#pragma unroll
        for (int i = 0; i < 8; i++) {
            d += k[i].x * vp[i].x + k[i].y * vp[i].y +
                 k[i].z * vp[i].z + k[i].w * vp[i].w;
        }
#pragma unroll
        for (int off = 16; off; off >>= 1)
            d += __shfl_xor_sync(0xffffffffu, d, off);

        if (lane == 0) g_scores[b * SLEN + s] = d;

        if (d > m) {  // warp-uniform; taken ~log2(64) times
            float sc = __expf(m - d);
            l *= sc;
#pragma unroll
            for (int i = 0; i < 8; i++) {
                acc[i].x *= sc; acc[i].y *= sc; acc[i].z *= sc; acc[i].w *= sc;
            }
            m = d;
        }
        float p = __expf(d - m);
        l += p;
#pragma unroll
        for (int i = 0; i < 8; i++) {
            acc[i].x += p * k[i].x; acc[i].y += p * k[i].y;
            acc[i].z += p * k[i].z; acc[i].w += p * k[i].w;
        }
    }

    // ---- block-level merge of 8 warp partials ----
#pragma unroll
    for (int i = 0; i < 8; i++) s_acc[w][i * 32 + lane] = acc[i];
    if (lane == 0) { s_m[w] = m; s_l[w] = l; }
    __syncthreads();

    // every thread: merged M/L (8 iterations, redundant but cheap)
    float M = s_m[0];
#pragma unroll
    for (int ww = 1; ww < NWARPS; ww++) M = fmaxf(M, s_m[ww]);
    float L = 0.0f;
    float scale[NWARPS];
#pragma unroll
    for (int ww = 0; ww < NWARPS; ww++) {
        scale[ww] = __expf(s_m[ww] - M);
        L += scale[ww] * s_l[ww];
    }

    // thread t reduces float4 column t across the 8 warps
    float4 sum = make_float4(0.f, 0.f, 0.f, 0.f);
#pragma unroll
    for (int ww = 0; ww < NWARPS; ww++) {
        float4 v = s_acc[ww][t];
        const float sc = scale[ww];
        sum.x += sc * v.x; sum.y += sc * v.y;
        sum.z += sc * v.z; sum.w += sc * v.w;
    }

    const int pidx = b * NPART + sb;
    reinterpret_cast<float4*>(g_pctx + (size_t)pidx * HDIM)[t] = sum;
    if (t == 0) { g_pm[pidx] = M; g_pl[pidx] = L; }
}

// ---------------------------------------------------------------------------
// K3: merge 8 partials per batch + emit outputs.
// grid (BATCH, 4), block 256. Block (b,chunk): context h4 in [chunk*64,+64),
// weights s in [chunk*1024,+1024). out layout: [context B*H | weight B*S]
// ---------------------------------------------------------------------------
__global__ void combine_kernel(float* __restrict__ out) {
    const int b     = blockIdx.x;
    const int chunk = blockIdx.y;     // 0..3
    const int t     = threadIdx.x;    // 0..255

    // every thread computes M/L over the 8 partials (cheap, no sync needed)
    float M = g_pm[b * NPART + 0];
#pragma unroll
    for (int p = 1; p < NPART; p++) M = fmaxf(M, g_pm[b * NPART + p]);
    float L = 0.0f;
    float sc[NPART];
#pragma unroll
    for (int p = 0; p < NPART; p++) {
        sc[p] = __expf(g_pm[b * NPART + p] - M);
        L += sc[p] * g_pl[b * NPART + p];
    }
    const float invL = 1.0f / L;

    // context
    if (t < 64) {
        const int h4 = chunk * 64 + t;
        float4 sum = make_float4(0.f, 0.f, 0.f, 0.f);
#pragma unroll
        for (int p = 0; p < NPART; p++) {
            float4 v = reinterpret_cast<const float4*>(
                g_pctx + (size_t)(b * NPART + p) * HDIM)[h4];
            sum.x += sc[p] * v.x; sum.y += sc[p] * v.y;
            sum.z += sc[p] * v.z; sum.w += sc[p] * v.w;
        }
        sum.x *= invL; sum.y *= invL; sum.z *= invL; sum.w *= invL;
        reinterpret_cast<float4*>(out + (size_t)b * HDIM)[h4] = sum;
    }

    // weights
    float* __restrict__ wout = out + (size_t)BATCH * HDIM + (size_t)b * SLEN;
    const float* __restrict__ sc_in = g_scores + (size_t)b * SLEN;
#pragma unroll
    for (int i = 0; i < 4; i++) {
        const int s = chunk * 1024 + i * 256 + t;
        wout[s] = __expf(sc_in[s] - M) * invL;
    }
}

// ---------------------------------------------------------------------------
extern "C" void kernel_launch(void* const* d_in, const int* in_sizes, int n_in,
                              void* d_out, int out_size) {
    // inputs (metadata order): query, keys, W, U, V
    const float* keys = (const float*)d_in[1];
    const float* U    = (const float*)d_in[3];
    const float* V    = (const float*)d_in[4];
    float* out = (float*)d_out;

    vprime_kernel<<<dim3(8, VCHUNKS), 128>>>(U, V);
    vreduce_kernel<<<8, 128>>>();
    main_pass_kernel<<<dim3(NSB, BATCH), 256>>>(keys);
    combine_kernel<<<dim3(BATCH, 4), 256>>>(out);
}